// round 1
// baseline (speedup 1.0000x reference)
#include <cuda_runtime.h>
#include <math.h>

#define T_TOK 8192
#define H_DIM 1024
#define F_DIM 4096
#define E_NUM 8

// ---- scratch (static device globals; no allocation at launch time) ----
__device__ int   g_count[E_NUM];
__device__ int   g_off[E_NUM];
__device__ int   g_tok[E_NUM * T_TOK];
__device__ float g_gate[E_NUM * T_TOK];
// total routed slots is exactly K*T = 16384 -> compact hidden buffer (268 MB)
__device__ float g_hidden[(size_t)2 * T_TOK * F_DIM];

__device__ __forceinline__ float gelu_tanh(float v) {
    const float c = 0.7978845608028654f;  // sqrt(2/pi)
    float u = c * (v + 0.044715f * v * v * v);
    return 0.5f * v * (1.0f + tanhf(u));
}

// ---- kernel 0: zero expert counts + output buffer ----
__global__ void zero_kernel(float* __restrict__ out, int out_size) {
    if (blockIdx.x == 0 && threadIdx.x < E_NUM) g_count[threadIdx.x] = 0;
    int stride = gridDim.x * blockDim.x;
    for (int i = blockIdx.x * blockDim.x + threadIdx.x; i < out_size; i += stride)
        out[i] = 0.0f;
}

// ---- kernel 1: router (warp per token): logits -> softmax -> top2 -> append ----
__global__ void router_kernel(const float* __restrict__ x, const float* __restrict__ rw) {
    int t = blockIdx.x * 8 + threadIdx.y;
    int lane = threadIdx.x;
    float acc[E_NUM];
#pragma unroll
    for (int e = 0; e < E_NUM; e++) acc[e] = 0.0f;

    const float* xrow = x + (size_t)t * H_DIM;
    for (int h = lane; h < H_DIM; h += 32) {
        float xv = xrow[h];
        const float4* r = (const float4*)(rw + (size_t)h * E_NUM);
        float4 r0 = r[0], r1 = r[1];
        acc[0] += xv * r0.x; acc[1] += xv * r0.y;
        acc[2] += xv * r0.z; acc[3] += xv * r0.w;
        acc[4] += xv * r1.x; acc[5] += xv * r1.y;
        acc[6] += xv * r1.z; acc[7] += xv * r1.w;
    }
#pragma unroll
    for (int e = 0; e < E_NUM; e++) {
#pragma unroll
        for (int off = 16; off > 0; off >>= 1)
            acc[e] += __shfl_xor_sync(0xffffffffu, acc[e], off);
    }

    if (lane == 0) {
        float m = acc[0];
#pragma unroll
        for (int e = 1; e < E_NUM; e++) m = fmaxf(m, acc[e]);
        float p[E_NUM];
        float s = 0.0f;
#pragma unroll
        for (int e = 0; e < E_NUM; e++) { p[e] = expf(acc[e] - m); s += p[e]; }
        float inv = 1.0f / s;

        int i1 = 0; float v1 = p[0];
#pragma unroll
        for (int e = 1; e < E_NUM; e++)
            if (p[e] > v1) { v1 = p[e]; i1 = e; }
        int i2 = -1; float v2 = -1.0f;
#pragma unroll
        for (int e = 0; e < E_NUM; e++)
            if (e != i1 && p[e] > v2) { v2 = p[e]; i2 = e; }

        int s1 = atomicAdd(&g_count[i1], 1);
        g_tok[i1 * T_TOK + s1]  = t;
        g_gate[i1 * T_TOK + s1] = v1 * inv;
        int s2 = atomicAdd(&g_count[i2], 1);
        g_tok[i2 * T_TOK + s2]  = t;
        g_gate[i2 * T_TOK + s2] = v2 * inv;
    }
}

// ---- kernel 2: exclusive prefix over 8 counts ----
__global__ void scan_kernel() {
    if (threadIdx.x == 0) {
        int s = 0;
#pragma unroll
        for (int e = 0; e < E_NUM; e++) { g_off[e] = s; s += g_count[e]; }
    }
}

// ---- kernel 3: fc1 + GELU. C[slot][f] = gelu( gather(x)[slot] . w1[e][:,f] ) ----
// 128x128 tile, BK=8, 256 threads, 8x8 per-thread microtile.
__global__ void __launch_bounds__(256, 2)
fc1_kernel(const float* __restrict__ x, const float* __restrict__ w1) {
    const int e = blockIdx.z;
    const int n = g_count[e];
    const int row0 = blockIdx.y * 128;
    if (row0 >= n) return;
    const int col0 = blockIdx.x * 128;
    const float* B = w1 + (size_t)e * ((size_t)H_DIM * F_DIM);

    __shared__ float As[8][128];
    __shared__ float Bs[8][128];

    const int tid = threadIdx.x;
    const int a_row = tid >> 1;
    const int a_k4  = (tid & 1) << 2;
    const int grow  = row0 + a_row;
    const float* a_ptr = 0;
    if (grow < n) a_ptr = x + (size_t)g_tok[e * T_TOK + grow] * H_DIM + a_k4;

    const int b_k = tid >> 5;
    const int b_c = (tid & 31) << 2;
    const float* b_ptr = B + (size_t)b_k * F_DIM + col0 + b_c;

    float acc[8][8];
#pragma unroll
    for (int i = 0; i < 8; i++)
#pragma unroll
        for (int j = 0; j < 8; j++) acc[i][j] = 0.0f;

    const int ty = tid >> 4, tx = tid & 15;

    float4 av = a_ptr ? *(const float4*)(a_ptr) : make_float4(0.f, 0.f, 0.f, 0.f);
    float4 bv = *(const float4*)(b_ptr);

    for (int k0 = 0; k0 < H_DIM; k0 += 8) {
        As[a_k4 + 0][a_row] = av.x;
        As[a_k4 + 1][a_row] = av.y;
        As[a_k4 + 2][a_row] = av.z;
        As[a_k4 + 3][a_row] = av.w;
        *(float4*)&Bs[b_k][b_c] = bv;
        __syncthreads();
        if (k0 + 8 < H_DIM) {
            av = a_ptr ? *(const float4*)(a_ptr + k0 + 8) : make_float4(0.f, 0.f, 0.f, 0.f);
            bv = *(const float4*)(b_ptr + (size_t)(k0 + 8) * F_DIM);
        }
#pragma unroll
        for (int kk = 0; kk < 8; kk++) {
            float a[8], b[8];
            *(float4*)&a[0] = *(const float4*)&As[kk][ty * 8];
            *(float4*)&a[4] = *(const float4*)&As[kk][ty * 8 + 4];
            *(float4*)&b[0] = *(const float4*)&Bs[kk][tx * 8];
            *(float4*)&b[4] = *(const float4*)&Bs[kk][tx * 8 + 4];
#pragma unroll
            for (int i = 0; i < 8; i++)
#pragma unroll
                for (int j = 0; j < 8; j++)
                    acc[i][j] = fmaf(a[i], b[j], acc[i][j]);
        }
        __syncthreads();
    }

    const int hrow0 = g_off[e];
#pragma unroll
    for (int i = 0; i < 8; i++) {
        int r = row0 + ty * 8 + i;
        if (r < n) {
            float* dst = g_hidden + (size_t)(hrow0 + r) * F_DIM + col0 + tx * 8;
            float4 v0, v1;
            v0.x = gelu_tanh(acc[i][0]); v0.y = gelu_tanh(acc[i][1]);
            v0.z = gelu_tanh(acc[i][2]); v0.w = gelu_tanh(acc[i][3]);
            v1.x = gelu_tanh(acc[i][4]); v1.y = gelu_tanh(acc[i][5]);
            v1.z = gelu_tanh(acc[i][6]); v1.w = gelu_tanh(acc[i][7]);
            *(float4*)dst       = v0;
            *(float4*)(dst + 4) = v1;
        }
    }
}

// ---- kernel 4: fc2 + weighted combine. out[tok] += gate * (hidden[slot] . w2[e]) ----
__global__ void __launch_bounds__(256, 2)
fc2_kernel(const float* __restrict__ w2, float* __restrict__ out) {
    const int e = blockIdx.z;
    const int n = g_count[e];
    const int row0 = blockIdx.y * 128;
    if (row0 >= n) return;
    const int col0 = blockIdx.x * 128;
    const float* B = w2 + (size_t)e * ((size_t)F_DIM * H_DIM);
    const float* A = g_hidden + (size_t)g_off[e] * F_DIM;

    __shared__ float As[8][128];
    __shared__ float Bs[8][128];

    const int tid = threadIdx.x;
    const int a_row = tid >> 1;
    const int a_k4  = (tid & 1) << 2;
    const int grow  = row0 + a_row;
    const float* a_ptr = 0;
    if (grow < n) a_ptr = A + (size_t)grow * F_DIM + a_k4;

    const int b_k = tid >> 5;
    const int b_c = (tid & 31) << 2;
    const float* b_ptr = B + (size_t)b_k * H_DIM + col0 + b_c;

    float acc[8][8];
#pragma unroll
    for (int i = 0; i < 8; i++)
#pragma unroll
        for (int j = 0; j < 8; j++) acc[i][j] = 0.0f;

    const int ty = tid >> 4, tx = tid & 15;

    float4 av = a_ptr ? *(const float4*)(a_ptr) : make_float4(0.f, 0.f, 0.f, 0.f);
    float4 bv = *(const float4*)(b_ptr);

    for (int k0 = 0; k0 < F_DIM; k0 += 8) {
        As[a_k4 + 0][a_row] = av.x;
        As[a_k4 + 1][a_row] = av.y;
        As[a_k4 + 2][a_row] = av.z;
        As[a_k4 + 3][a_row] = av.w;
        *(float4*)&Bs[b_k][b_c] = bv;
        __syncthreads();
        if (k0 + 8 < F_DIM) {
            av = a_ptr ? *(const float4*)(a_ptr + k0 + 8) : make_float4(0.f, 0.f, 0.f, 0.f);
            bv = *(const float4*)(b_ptr + (size_t)(k0 + 8) * H_DIM);
        }
#pragma unroll
        for (int kk = 0; kk < 8; kk++) {
            float a[8], b[8];
            *(float4*)&a[0] = *(const float4*)&As[kk][ty * 8];
            *(float4*)&a[4] = *(const float4*)&As[kk][ty * 8 + 4];
            *(float4*)&b[0] = *(const float4*)&Bs[kk][tx * 8];
            *(float4*)&b[4] = *(const float4*)&Bs[kk][tx * 8 + 4];
#pragma unroll
            for (int i = 0; i < 8; i++)
#pragma unroll
                for (int j = 0; j < 8; j++)
                    acc[i][j] = fmaf(a[i], b[j], acc[i][j]);
        }
        __syncthreads();
    }

#pragma unroll
    for (int i = 0; i < 8; i++) {
        int r = row0 + ty * 8 + i;
        if (r < n) {
            int tok = g_tok[e * T_TOK + r];
            float gate = g_gate[e * T_TOK + r];
            float* dst = out + (size_t)tok * H_DIM + col0 + tx * 8;
#pragma unroll
            for (int j = 0; j < 8; j++)
                atomicAdd(&dst[j], gate * acc[i][j]);
        }
    }
}

extern "C" void kernel_launch(void* const* d_in, const int* in_sizes, int n_in,
                              void* d_out, int out_size) {
    const float* x   = (const float*)d_in[0];
    const float* rw  = (const float*)d_in[1];
    const float* w1  = (const float*)d_in[2];
    const float* w2  = (const float*)d_in[3];
    float* out = (float*)d_out;

    zero_kernel<<<2048, 256>>>(out, out_size);
    router_kernel<<<T_TOK / 8, dim3(32, 8)>>>(x, rw);
    scan_kernel<<<1, 32>>>();
    fc1_kernel<<<dim3(F_DIM / 128, T_TOK / 128, E_NUM), 256>>>(x, w1);
    fc2_kernel<<<dim3(H_DIM / 128, T_TOK / 128, E_NUM), 256>>>(w2, out);
}

// round 3
// speedup vs baseline: 2.2276x; 2.2276x over previous
#include <cuda_runtime.h>
#include <math.h>
#include <stdint.h>

#define T_TOK 8192
#define H_DIM 1024
#define F_DIM 4096
#define E_NUM 8

// ---- scratch (static device globals; no allocation at launch time) ----
__device__ int   g_count[E_NUM];
__device__ int   g_off[E_NUM];
__device__ int   g_tok[E_NUM * T_TOK];
__device__ float g_gate[E_NUM * T_TOK];
__device__ float g_hidden[(size_t)2 * T_TOK * F_DIM];

__device__ __forceinline__ uint32_t f2tf32(float f) {
    uint32_t u; asm("cvt.rna.tf32.f32 %0, %1;" : "=r"(u) : "f"(f)); return u;
}

__device__ __forceinline__ void mma_tf32(float* c, const uint32_t* a, const uint32_t* b) {
    asm volatile(
        "mma.sync.aligned.m16n8k8.row.col.f32.tf32.tf32.f32 "
        "{%0,%1,%2,%3}, {%4,%5,%6,%7}, {%8,%9}, {%0,%1,%2,%3};"
        : "+f"(c[0]), "+f"(c[1]), "+f"(c[2]), "+f"(c[3])
        : "r"(a[0]), "r"(a[1]), "r"(a[2]), "r"(a[3]), "r"(b[0]), "r"(b[1]));
}

__device__ __forceinline__ float gelu_tanh(float v) {
    const float c = 0.7978845608028654f;
    float u = c * (v + 0.044715f * v * v * v);
    return 0.5f * v * (1.0f + tanhf(u));
}

// ======================= small kernels =======================
__global__ void zero_kernel(float* __restrict__ out, int out_size) {
    if (blockIdx.x == 0 && threadIdx.x < E_NUM) g_count[threadIdx.x] = 0;
    int stride = gridDim.x * blockDim.x;
    for (int i = blockIdx.x * blockDim.x + threadIdx.x; i < out_size; i += stride)
        out[i] = 0.0f;
}

__global__ void router_kernel(const float* __restrict__ x, const float* __restrict__ rw) {
    int t = blockIdx.x * 8 + threadIdx.y;
    int lane = threadIdx.x;
    float acc[E_NUM];
#pragma unroll
    for (int e = 0; e < E_NUM; e++) acc[e] = 0.0f;
    const float* xrow = x + (size_t)t * H_DIM;
    for (int h = lane; h < H_DIM; h += 32) {
        float xv = xrow[h];
        const float4* r = (const float4*)(rw + (size_t)h * E_NUM);
        float4 r0 = r[0], r1 = r[1];
        acc[0] += xv * r0.x; acc[1] += xv * r0.y;
        acc[2] += xv * r0.z; acc[3] += xv * r0.w;
        acc[4] += xv * r1.x; acc[5] += xv * r1.y;
        acc[6] += xv * r1.z; acc[7] += xv * r1.w;
    }
#pragma unroll
    for (int e = 0; e < E_NUM; e++) {
#pragma unroll
        for (int off = 16; off > 0; off >>= 1)
            acc[e] += __shfl_xor_sync(0xffffffffu, acc[e], off);
    }
    if (lane == 0) {
        float m = acc[0];
#pragma unroll
        for (int e = 1; e < E_NUM; e++) m = fmaxf(m, acc[e]);
        float p[E_NUM]; float s = 0.0f;
#pragma unroll
        for (int e = 0; e < E_NUM; e++) { p[e] = expf(acc[e] - m); s += p[e]; }
        float inv = 1.0f / s;
        int i1 = 0; float v1 = p[0];
#pragma unroll
        for (int e = 1; e < E_NUM; e++) if (p[e] > v1) { v1 = p[e]; i1 = e; }
        int i2 = -1; float v2 = -1.0f;
#pragma unroll
        for (int e = 0; e < E_NUM; e++) if (e != i1 && p[e] > v2) { v2 = p[e]; i2 = e; }
        int s1 = atomicAdd(&g_count[i1], 1);
        g_tok[i1 * T_TOK + s1]  = t;
        g_gate[i1 * T_TOK + s1] = v1 * inv;
        int s2 = atomicAdd(&g_count[i2], 1);
        g_tok[i2 * T_TOK + s2]  = t;
        g_gate[i2 * T_TOK + s2] = v2 * inv;
    }
}

__global__ void scan_kernel() {
    if (threadIdx.x == 0) {
        int s = 0;
#pragma unroll
        for (int e = 0; e < E_NUM; e++) { g_off[e] = s; s += g_count[e]; }
    }
}

// ======================= tensor-core grouped GEMM =======================
// 128x128 tile, BK=16, 256 threads (8 warps in 2Mx4N), warp tile 64x32,
// mma.sync m16n8k8 tf32, fp32 accumulate. A gathered rows, B = expert weights.
template<int KTOT, int LDB, bool FC1>
__global__ void __launch_bounds__(256, 2)
moe_gemm(const float* __restrict__ Asrc, const float* __restrict__ W,
         float* __restrict__ Out)
{
    const int e = blockIdx.z;
    const int n = g_count[e];
    const int row0 = blockIdx.y * 128;
    if (row0 >= n) return;
    const int col0 = blockIdx.x * 128;

    __shared__ uint32_t As[16][132];   // [k][m]
    __shared__ uint32_t Bs[16][132];   // [k][n]

    const int tid = threadIdx.x;
    const int lane = tid & 31;
    const int w = tid >> 5;
    const int wm = w & 1;        // 0..1  (64 rows each)
    const int wn = w >> 1;       // 0..3  (32 cols each)

    // ---- global load mapping ----
    const int am = tid >> 1;             // A row 0..127
    const int ak = (tid & 1) * 8;        // k half
    const float* aptr = nullptr;
    if (row0 + am < n) {
        if (FC1) aptr = Asrc + (size_t)g_tok[e * T_TOK + row0 + am] * H_DIM + ak;
        else     aptr = g_hidden + (size_t)(g_off[e] + row0 + am) * F_DIM + ak;
    }
    const int bk = tid >> 4;             // B k-row 0..15
    const int bn = (tid & 15) * 8;       // col
    const float* bptr = W + (size_t)e * KTOT * LDB + (size_t)bk * LDB + col0 + bn;

    float acc[4][4][4];
#pragma unroll
    for (int i = 0; i < 4; i++)
#pragma unroll
        for (int j = 0; j < 4; j++)
#pragma unroll
            for (int q = 0; q < 4; q++) acc[i][j][q] = 0.0f;

    float4 ra0, ra1, rb0, rb1;
    auto load_regs = [&](int k0) {
        if (aptr) {
            ra0 = *(const float4*)(aptr + k0);
            ra1 = *(const float4*)(aptr + k0 + 4);
        } else {
            ra0 = make_float4(0.f, 0.f, 0.f, 0.f);
            ra1 = ra0;
        }
        const float* bp = bptr + (size_t)k0 * LDB;
        rb0 = *(const float4*)(bp);
        rb1 = *(const float4*)(bp + 4);
    };

    load_regs(0);
    for (int k0 = 0; k0 < KTOT; k0 += 16) {
        // store current tile to smem (tf32-converted)
        As[ak + 0][am] = f2tf32(ra0.x);
        As[ak + 1][am] = f2tf32(ra0.y);
        As[ak + 2][am] = f2tf32(ra0.z);
        As[ak + 3][am] = f2tf32(ra0.w);
        As[ak + 4][am] = f2tf32(ra1.x);
        As[ak + 5][am] = f2tf32(ra1.y);
        As[ak + 6][am] = f2tf32(ra1.z);
        As[ak + 7][am] = f2tf32(ra1.w);
        {
            uint4 v0 = make_uint4(f2tf32(rb0.x), f2tf32(rb0.y), f2tf32(rb0.z), f2tf32(rb0.w));
            uint4 v1 = make_uint4(f2tf32(rb1.x), f2tf32(rb1.y), f2tf32(rb1.z), f2tf32(rb1.w));
            *(uint4*)&Bs[bk][bn]     = v0;
            *(uint4*)&Bs[bk][bn + 4] = v1;
        }
        __syncthreads();
        if (k0 + 16 < KTOT) load_regs(k0 + 16);

#pragma unroll
        for (int kq = 0; kq < 16; kq += 8) {
            const int kr = kq + (lane & 3);
            uint32_t af[4][4], bf[4][2];
#pragma unroll
            for (int mf = 0; mf < 4; mf++) {
                int m = wm * 64 + mf * 16 + (lane >> 2);
                af[mf][0] = As[kr][m];
                af[mf][1] = As[kr][m + 8];
                af[mf][2] = As[kr + 4][m];
                af[mf][3] = As[kr + 4][m + 8];
            }
#pragma unroll
            for (int nf = 0; nf < 4; nf++) {
                int nn = wn * 32 + nf * 8 + (lane >> 2);
                bf[nf][0] = Bs[kr][nn];
                bf[nf][1] = Bs[kr + 4][nn];
            }
#pragma unroll
            for (int mf = 0; mf < 4; mf++)
#pragma unroll
                for (int nf = 0; nf < 4; nf++)
                    mma_tf32(acc[mf][nf], af[mf], bf[nf]);
        }
        __syncthreads();
    }

    // ---- epilogue ----
    if (FC1) {
        const int hrow0 = g_off[e];
#pragma unroll
        for (int mf = 0; mf < 4; mf++) {
            int rlo = row0 + wm * 64 + mf * 16 + (lane >> 2);
            int rhi = rlo + 8;
            float* dlo = g_hidden + (size_t)(hrow0 + rlo) * F_DIM;
            float* dhi = g_hidden + (size_t)(hrow0 + rhi) * F_DIM;
#pragma unroll
            for (int nf = 0; nf < 4; nf++) {
                int c = col0 + wn * 32 + nf * 8 + 2 * (lane & 3);
                if (rlo < n) {
                    float2 v = make_float2(gelu_tanh(acc[mf][nf][0]),
                                           gelu_tanh(acc[mf][nf][1]));
                    *(float2*)(dlo + c) = v;
                }
                if (rhi < n) {
                    float2 v = make_float2(gelu_tanh(acc[mf][nf][2]),
                                           gelu_tanh(acc[mf][nf][3]));
                    *(float2*)(dhi + c) = v;
                }
            }
        }
    } else {
#pragma unroll
        for (int mf = 0; mf < 4; mf++) {
            int rlo = row0 + wm * 64 + mf * 16 + (lane >> 2);
            int rhi = rlo + 8;
            int tok_lo = 0, tok_hi = 0; float g_lo = 0.f, g_hi = 0.f;
            if (rlo < n) { tok_lo = g_tok[e * T_TOK + rlo]; g_lo = g_gate[e * T_TOK + rlo]; }
            if (rhi < n) { tok_hi = g_tok[e * T_TOK + rhi]; g_hi = g_gate[e * T_TOK + rhi]; }
            float* olo = Out + (size_t)tok_lo * H_DIM;
            float* ohi = Out + (size_t)tok_hi * H_DIM;
#pragma unroll
            for (int nf = 0; nf < 4; nf++) {
                int c = col0 + wn * 32 + nf * 8 + 2 * (lane & 3);
                if (rlo < n) {
                    atomicAdd(olo + c,     g_lo * acc[mf][nf][0]);
                    atomicAdd(olo + c + 1, g_lo * acc[mf][nf][1]);
                }
                if (rhi < n) {
                    atomicAdd(ohi + c,     g_hi * acc[mf][nf][2]);
                    atomicAdd(ohi + c + 1, g_hi * acc[mf][nf][3]);
                }
            }
        }
    }
}

// ======================= launch =======================
extern "C" void kernel_launch(void* const* d_in, const int* in_sizes, int n_in,
                              void* d_out, int out_size) {
    const float* x  = (const float*)d_in[0];
    const float* rw = (const float*)d_in[1];
    const float* w1 = (const float*)d_in[2];
    const float* w2 = (const float*)d_in[3];
    float* out = (float*)d_out;

    zero_kernel<<<2048, 256>>>(out, out_size);
    router_kernel<<<T_TOK / 8, dim3(32, 8)>>>(x, rw);
    scan_kernel<<<1, 32>>>();
    moe_gemm<H_DIM, F_DIM, true ><<<dim3(F_DIM / 128, T_TOK / 128, E_NUM), 256>>>(x, w1, nullptr);
    moe_gemm<F_DIM, H_DIM, false><<<dim3(H_DIM / 128, T_TOK / 128, E_NUM), 256>>>(nullptr, w2, out);
}